// round 17
// baseline (speedup 1.0000x reference)
#include <cuda_runtime.h>
#include <cuda_fp16.h>
#include <cstdint>

// ============================================================================
// StyleGAN2 ModulatedConv2D via Winograd F(2x2,3x3) + HMMA mma.sync.
//   U[xi][co][ci] = G w G^T            (weight transform, fp16, 16 mats)
//   D[xi][tg][ci] = B^T (s*x patch) B  (input transform + modulation, fp16)
// R14 resubmit (R15): FUSED gemm+combine with epilogue pitch 66 (even) fixing
//   the misaligned float2 smem load. M never materialized; per-xi fold of the
//   M fragment into 4 output accumulators; epilogue writes out directly.
// ============================================================================

#define CIN     512
#define COUT    512
#define LATENTD 512
#define NBATCH  8
#define HW      4096
#define NTILES  8192              // 8 * 32 * 32
#define NCHTOT  256               // 16 xi * 16 chunks (K=512, chunk 32)
#define PITCH   80                // 64B payload + 16B pad
#define STG_B   (128 * PITCH)     // A(64 rows) + B(64 rows) = 10240
#define YPITCH  66                // EVEN float pitch -> aligned float2 reads
#define YSM_B   (256 * YPITCH * 4)          // 67584
#define SMEM_SZ YSM_B             // dynamic smem (covers 4*STG_B=40960 too)

#define XT_PITCH 35
#define XT_SMEM  (10 * 64 * XT_PITCH * 4)   // 89600

#define RC_W 0.014731391274719738f   // 1/sqrt(9*512)
#define RC_S 0.04419417382415922f    // 1/sqrt(512)

__device__ float g_style[NBATCH * CIN];
__device__ float g_demod[NBATCH * COUT];
__device__ float g_wsq[CIN * COUT];
__device__ __align__(16) __half g_U[(size_t)16 * COUT * CIN];    // [xi][co][ci]
__device__ __align__(16) __half g_D[(size_t)16 * NTILES * CIN];  // [xi][tg][ci]

// ---------------- PTX helpers ----------------------------------------------
__device__ __forceinline__ uint32_t smem_u32(const void* p) {
    uint32_t a;
    asm("{ .reg .u64 t; cvta.to.shared.u64 t, %1; cvt.u32.u64 %0, t; }"
        : "=r"(a) : "l"(p));
    return a;
}
__device__ __forceinline__ void cp16(uint32_t s, const void* g) {
    asm volatile("cp.async.cg.shared.global [%0], [%1], 16;"
                 :: "r"(s), "l"(g) : "memory");
}
#define CP_COMMIT() asm volatile("cp.async.commit_group;" ::: "memory")
#define CP_WAIT2()  asm volatile("cp.async.wait_group 2;" ::: "memory")
#define CP_WAIT0()  asm volatile("cp.async.wait_group 0;" ::: "memory")

#define LDSM4(r, addr) \
    asm volatile("ldmatrix.sync.aligned.m8n8.x4.shared.b16 {%0,%1,%2,%3}, [%4];" \
                 : "=r"((r)[0]), "=r"((r)[1]), "=r"((r)[2]), "=r"((r)[3]) \
                 : "r"(addr))

#define MMA16816(d, a, b0, b1) \
    asm volatile("mma.sync.aligned.m16n8k16.row.col.f32.f16.f16.f32 " \
                 "{%0,%1,%2,%3},{%4,%5,%6,%7},{%8,%9},{%0,%1,%2,%3};" \
                 : "+f"((d)[0]), "+f"((d)[1]), "+f"((d)[2]), "+f"((d)[3]) \
                 : "r"((a)[0]), "r"((a)[1]), "r"((a)[2]), "r"((a)[3]), \
                   "r"(b0), "r"(b1))

// ---------------- style / demod (validated since R3) ------------------------
__global__ void style_k(const float* __restrict__ dl,
                        const float* __restrict__ mw,
                        const float* __restrict__ mb) {
    const int n = blockIdx.x, ci = threadIdx.x;
    __shared__ float dls[LATENTD];
    dls[ci] = dl[n * LATENTD + ci];
    __syncthreads();
    float acc = 0.0f;
#pragma unroll 8
    for (int l = 0; l < LATENTD; l++) acc += dls[l] * mw[l * CIN + ci];
    g_style[n * CIN + ci] = acc * RC_S + mb[ci] + 1.0f;
}

__global__ void demod_k() {
    const int n = blockIdx.x, co = threadIdx.x;
    __shared__ float s2[CIN];
    float sv = g_style[n * CIN + co];
    s2[co] = sv * sv;
    __syncthreads();
    float acc = 0.0f;
#pragma unroll 8
    for (int ci = 0; ci < CIN; ci++) acc += s2[ci] * g_wsq[ci * COUT + co];
    g_demod[n * COUT + co] = rsqrtf(acc * (RC_W * RC_W) + 1e-8f);
}

// ---------------- weight transform: U = G w G^T (+ wsq) ---------------------
__global__ void wT_k(const float* __restrict__ w) {
    __shared__ float sw[9][32][33];
    const int tx = threadIdx.x, ty = threadIdx.y;
    const int ci0 = blockIdx.x * 32, co0 = blockIdx.y * 32;
#pragma unroll
    for (int kk = 0; kk < 9; kk++)
#pragma unroll
        for (int r = 0; r < 4; r++)
            sw[kk][ty + r * 8][tx] =
                w[((size_t)kk * CIN + ci0 + ty + r * 8) * COUT + co0 + tx];
    __syncthreads();
#pragma unroll
    for (int q = 0; q < 4; q++) {
        const int col = ty + q * 8;
        const int ci = ci0 + tx, co = co0 + col;
        float g[9], sq = 0.0f;
#pragma unroll
        for (int kk = 0; kk < 9; kk++) {
            g[kk] = sw[kk][tx][col];
            sq += g[kk] * g[kk];
        }
        g_wsq[ci * COUT + co] = sq;
        float t[4][3];
#pragma unroll
        for (int c = 0; c < 3; c++) {
            const float a = g[c], b = g[3 + c], d = g[6 + c];
            t[0][c] = a;
            t[1][c] = 0.5f * (a + b + d);
            t[2][c] = 0.5f * (a - b + d);
            t[3][c] = d;
        }
#pragma unroll
        for (int r = 0; r < 4; r++) {
            const float a = t[r][0], b = t[r][1], d = t[r][2];
            float u[4];
            u[0] = a;
            u[1] = 0.5f * (a + b + d);
            u[2] = 0.5f * (a - b + d);
            u[3] = d;
#pragma unroll
            for (int c = 0; c < 4; c++)
                g_U[((size_t)(r * 4 + c) * COUT + co) * CIN + ci] =
                    __float2half(u[c]);
        }
    }
}

// ---------------- input transform: D = B^T (s*d) B ---------------------------
__global__ void xT_k(const float* __restrict__ x) {
    extern __shared__ __align__(16) float si[];   // [10 rows][64 px][pitch 35]
    const int tid = threadIdx.x;
    const int ci0 = blockIdx.x * 32, by = blockIdx.y, n = blockIdx.z;

    const int px = tid & 63, sub = tid >> 6;
#pragma unroll
    for (int it = 0; it < 80; it++) {
        const int pair = it * 4 + sub;
        const int row = pair >> 5, ci_l = pair & 31;
        const int gy = 8 * by - 1 + row;
        const float v = ((unsigned)gy < 64u)
            ? x[((size_t)(n * CIN + ci0 + ci_l) * 64 + gy) * 64 + px] : 0.0f;
        si[(row * 64 + px) * XT_PITCH + ci_l] = v;
    }
    __syncthreads();

    const int cp = tid & 15;
    const int tgrp = tid >> 4;
    const float sv0 = g_style[n * CIN + ci0 + 2 * cp];
    const float sv1 = g_style[n * CIN + ci0 + 2 * cp + 1];

#pragma unroll
    for (int ty_l = 0; ty_l < 4; ty_l++) {
#pragma unroll
        for (int tt = 0; tt < 2; tt++) {
            const int tx = tgrp + tt * 16;
            const int tg = n * 1024 + (4 * by + ty_l) * 32 + tx;
            float d0[4][4], d1[4][4];
#pragma unroll
            for (int i = 0; i < 4; i++)
#pragma unroll
                for (int j = 0; j < 4; j++) {
                    const int pxx = 2 * tx - 1 + j;
                    if ((unsigned)pxx < 64u) {
                        const float* p =
                            &si[((2 * ty_l + i) * 64 + pxx) * XT_PITCH + 2 * cp];
                        d0[i][j] = p[0] * sv0;
                        d1[i][j] = p[1] * sv1;
                    } else { d0[i][j] = 0.0f; d1[i][j] = 0.0f; }
                }
            float e0[4][4], e1[4][4];
#pragma unroll
            for (int j = 0; j < 4; j++) {
                e0[0][j] = d0[0][j] - d0[2][j];  e1[0][j] = d1[0][j] - d1[2][j];
                e0[1][j] = d0[1][j] + d0[2][j];  e1[1][j] = d1[1][j] + d1[2][j];
                e0[2][j] = d0[2][j] - d0[1][j];  e1[2][j] = d1[2][j] - d1[1][j];
                e0[3][j] = d0[1][j] - d0[3][j];  e1[3][j] = d1[1][j] - d1[3][j];
            }
            __half* dst = &g_D[(size_t)tg * CIN + ci0 + 2 * cp];
#pragma unroll
            for (int i = 0; i < 4; i++) {
                float f0[4], f1[4];
                f0[0] = e0[i][0] - e0[i][2];  f1[0] = e1[i][0] - e1[i][2];
                f0[1] = e0[i][1] + e0[i][2];  f1[1] = e1[i][1] + e1[i][2];
                f0[2] = e0[i][2] - e0[i][1];  f1[2] = e1[i][2] - e1[i][1];
                f0[3] = e0[i][1] - e0[i][3];  f1[3] = e1[i][1] - e1[i][3];
#pragma unroll
                for (int j = 0; j < 4; j++)
                    *(__half2*)(dst + (size_t)(i * 4 + j) * NTILES * CIN) =
                        __floats2half2_rn(f0[j], f1[j]);
            }
        }
    }
}

// ---------------- fused GEMM + A^T M A combine -------------------------------
// CTA: 64 tiles x 64 co, 8 warps (2m x 4n), warp tile 32x16.
// K runs 16 xi * 512 = one continuous 256-chunk pipeline (4 stages, dist 3).
__global__ void __launch_bounds__(256, 2) gemm_k(float* __restrict__ out) {
    extern __shared__ __align__(128) char dsm[];

    const int tid = threadIdx.x;
    const int wid = tid >> 5, lane = tid & 31;
    const int co0 = blockIdx.x * 64;
    const int m0 = blockIdx.y * 64;           // global tile base (same image)
    const int n = m0 >> 10;                   // image
    const int ty0 = (m0 & 1023) >> 5;         // tile-row base (2 rows per CTA)
    const int wm = (wid & 1) * 32;
    const int wn = (wid >> 1) * 16;

    const uint32_t sbase = smem_u32(dsm);

    // loaders: tid<128 -> A rows 0..63, tid>=128 -> B rows 0..63 (smem 64+)
    const int lrow = (tid >> 1) & 63;
    const int half = tid & 1;
    const uint32_t rc_st = (uint32_t)((tid >> 1) * PITCH + half * 32);
    const bool isA = tid < 128;
    const __half* row_base = isA
        ? g_D + (size_t)(m0 + lrow) * CIN + half * 16
        : g_U + (size_t)(co0 + lrow) * CIN + half * 16;
    const size_t xi_stride = isA ? (size_t)NTILES * CIN : (size_t)COUT * CIN;

    auto issue = [&](int j, int st) {
        const __half* g = row_base + (size_t)(j >> 4) * xi_stride +
                          ((j & 15) << 5);
        const uint32_t ab = sbase + st * STG_B + rc_st;
        cp16(ab, g);
        cp16(ab + 16, g + 8);
    };

    // ldmatrix per-lane offsets (ks adds +32)
    uint32_t a_off[2];
#pragma unroll
    for (int mt = 0; mt < 2; mt++)
        a_off[mt] = (uint32_t)((wm + mt * 16 + (lane & 15)) * PITCH +
                               (lane >> 4) * 16);
    const uint32_t b_off = (uint32_t)(
        (64 + wn + (lane & 7) + ((lane >> 4) & 1) * 8) * PITCH +
        ((lane >> 3) & 1) * 16);

    float macc[2][2][4];                      // M fragment for current xi
    float yacc[4][2][2][4];                   // 4 output positions
#pragma unroll
    for (int mt = 0; mt < 2; mt++)
#pragma unroll
        for (int nt = 0; nt < 2; nt++)
#pragma unroll
            for (int r = 0; r < 4; r++) {
                macc[mt][nt][r] = 0.0f;
#pragma unroll
                for (int p = 0; p < 4; p++) yacc[p][mt][nt][r] = 0.0f;
            }

    issue(0, 0); CP_COMMIT();
    issue(1, 1); CP_COMMIT();
    issue(2, 2); CP_COMMIT();

    for (int i = 0; i < NCHTOT; i++) {
        CP_WAIT2();
        __syncthreads();
        const uint32_t stB = sbase + (i & 3) * STG_B;
#pragma unroll
        for (int ks = 0; ks < 2; ks++) {
            uint32_t af[2][4], bf[4];
            LDSM4(af[0], stB + a_off[0] + ks * 32);
            LDSM4(af[1], stB + a_off[1] + ks * 32);
            LDSM4(bf, stB + b_off + ks * 32);
#pragma unroll
            for (int mt = 0; mt < 2; mt++) {
                MMA16816(macc[mt][0], af[mt], bf[0], bf[1]);
                MMA16816(macc[mt][1], af[mt], bf[2], bf[3]);
            }
        }
        if ((i & 15) == 15) {                 // xi complete -> fold into yacc
            const int xi = i >> 4;
            const int xr = xi >> 2, xc = xi & 3;
            const float cy0 = (xr == 3) ? 0.f : 1.f;
            const float cy1 = (xr == 0) ? 0.f : ((xr == 1) ? 1.f : -1.f);
            const float cx0 = (xc == 3) ? 0.f : 1.f;
            const float cx1 = (xc == 0) ? 0.f : ((xc == 1) ? 1.f : -1.f);
            const float c00 = cy0 * cx0, c01 = cy0 * cx1;
            const float c10 = cy1 * cx0, c11 = cy1 * cx1;
#pragma unroll
            for (int mt = 0; mt < 2; mt++)
#pragma unroll
                for (int nt = 0; nt < 2; nt++)
#pragma unroll
                    for (int r = 0; r < 4; r++) {
                        const float m = macc[mt][nt][r];
                        yacc[0][mt][nt][r] += c00 * m;
                        yacc[1][mt][nt][r] += c01 * m;
                        yacc[2][mt][nt][r] += c10 * m;
                        yacc[3][mt][nt][r] += c11 * m;
                        macc[mt][nt][r] = 0.0f;
                    }
        }
        if (i + 3 < NCHTOT) issue(i + 3, (i + 3) & 3);
        CP_COMMIT();
    }
    CP_WAIT0();
    __syncthreads();                          // pipeline smem -> reuse as ysm

    // ---- epilogue: demod scale, smem transpose, coalesced out writes ----
    // ysm row id = co_l*4 + py*2 + ty_l (256 rows), pitch YPITCH (even)
    float* ysm = (float*)dsm;
    float dmv[2][2];                          // [nt][col parity]
#pragma unroll
    for (int nt = 0; nt < 2; nt++)
#pragma unroll
        for (int q = 0; q < 2; q++)
            dmv[nt][q] = g_demod[n * COUT + co0 + wn + nt * 8 +
                                 (lane & 3) * 2 + q] * RC_W;
#pragma unroll
    for (int mt = 0; mt < 2; mt++)
#pragma unroll
        for (int nt = 0; nt < 2; nt++)
#pragma unroll
            for (int r = 0; r < 4; r++) {
                const int row_l = wm + mt * 16 + (lane >> 2) + (r >> 1) * 8;
                const int col_l = wn + nt * 8 + (lane & 3) * 2 + (r & 1);
                const int ty_l = row_l >> 5, tx_l = row_l & 31;
                const float dm = dmv[nt][r & 1];
#pragma unroll
                for (int p = 0; p < 4; p++) {
                    const int py = p >> 1, px = p & 1;
                    ysm[(col_l * 4 + py * 2 + ty_l) * YPITCH + tx_l * 2 + px] =
                        yacc[p][mt][nt][r] * dm;
                }
            }
    __syncthreads();

    // write: warp per row (32 lanes x float2 = 256B), 32 rows per warp
#pragma unroll 4
    for (int w8 = 0; w8 < 32; w8++) {
        const int row = wid + w8 * 8;
        const int co_l = row >> 2, py = (row >> 1) & 1, ty_l = row & 1;
        const float2 v = *(const float2*)&ysm[row * YPITCH + 2 * lane];
        const int y = 2 * (ty0 + ty_l) + py;
        *(float2*)&out[(((size_t)(n * COUT + co0 + co_l) * 64 + y) * 64) +
                       2 * lane] = v;
    }
}

// ---------------- launch -----------------------------------------------------
extern "C" void kernel_launch(void* const* d_in, const int* in_sizes, int n_in,
                              void* d_out, int out_size) {
    const float* x  = (const float*)d_in[0];   // [8,512,64,64]
    const float* dl = (const float*)d_in[1];   // [8,512]
    const float* w  = (const float*)d_in[2];   // [3,3,512,512]
    const float* mw = (const float*)d_in[3];   // [512,512]
    const float* mb = (const float*)d_in[4];   // [512]
    float* out = (float*)d_out;                // [8,512,64,64]

    cudaFuncSetAttribute(gemm_k, cudaFuncAttributeMaxDynamicSharedMemorySize,
                         SMEM_SZ);
    cudaFuncSetAttribute(xT_k, cudaFuncAttributeMaxDynamicSharedMemorySize,
                         XT_SMEM);

    style_k<<<NBATCH, 512>>>(dl, mw, mb);
    wT_k<<<dim3(CIN / 32, COUT / 32), dim3(32, 8)>>>(w);
    demod_k<<<NBATCH, 512>>>();
    xT_k<<<dim3(CIN / 32, 8, NBATCH), 256, XT_SMEM>>>(x);
    gemm_k<<<dim3(COUT / 64, NTILES / 64), 256, SMEM_SZ>>>(out);
}